// round 9
// baseline (speedup 1.0000x reference)
#include <cuda_runtime.h>
#include <cuda_fp16.h>
#include <math_constants.h>
#include <cstdint>

#define N_POS 3136
#define HW    56
#define MIDC  32
#define HEADS 8
#define INV   0.125f   // 1/sqrt(64)
#define LOG2E 1.4426950408889634f

// ---------------- scratch (global, no allocation in kernel_launch) ----------
__device__ float  g_q [HEADS * N_POS * MIDC];   // [h][p][m] fp32 (bias kernel reads)
__device__ __half g_k [HEADS * N_POS * MIDC];   // [h][p][m] fp16
__device__ __half g_vT[HEADS * MIDC * N_POS];   // [h][m][p] fp16 (transposed V)
__device__ float g_rowb[HEADS * N_POS * HW];    // log2e*inv-scaled row bias
__device__ float g_colb[HEADS * N_POS * HW];    // log2e*inv-scaled col bias
__device__ float g_o[MIDC * HEADS * N_POS];     // [channel = m*8+h][p]

// ---------------- helpers ----------------------------------------------------
__device__ __forceinline__ uint32_t pkh2(float lo, float hi) {
    uint32_t r;
    asm("cvt.rn.f16x2.f32 %0, %1, %2;" : "=r"(r) : "f"(hi), "f"(lo));
    return r;
}
__device__ __forceinline__ float ex2f(float x) {
    float r; asm("ex2.approx.ftz.f32 %0, %1;" : "=f"(r) : "f"(x)); return r;
}
__device__ __forceinline__ void mma_f16(
    float& d0, float& d1, float& d2, float& d3,
    uint32_t a0, uint32_t a1, uint32_t a2, uint32_t a3,
    uint32_t b0, uint32_t b1)
{
    asm("mma.sync.aligned.m16n8k16.row.col.f32.f16.f16.f32 "
        "{%0,%1,%2,%3}, {%4,%5,%6,%7}, {%8,%9}, {%0,%1,%2,%3};"
        : "+f"(d0), "+f"(d1), "+f"(d2), "+f"(d3)
        : "r"(a0), "r"(a1), "r"(a2), "r"(a3), "r"(b0), "r"(b1));
}
__device__ __forceinline__ void ldsm4(uint32_t& r0, uint32_t& r1, uint32_t& r2,
                                      uint32_t& r3, uint32_t a) {
    asm volatile("ldmatrix.sync.aligned.m8n8.x4.shared.b16 {%0,%1,%2,%3}, [%4];"
                 : "=r"(r0), "=r"(r1), "=r"(r2), "=r"(r3) : "r"(a));
}
__device__ __forceinline__ void stsm4(uint32_t a, uint32_t r0, uint32_t r1,
                                      uint32_t r2, uint32_t r3) {
    asm volatile("stmatrix.sync.aligned.m8n8.x4.shared.b16 [%0], {%1,%2,%3,%4};"
                 :: "r"(a), "r"(r0), "r"(r1), "r"(r2), "r"(r3) : "memory");
}
__device__ __forceinline__ void stsm2(uint32_t a, uint32_t r0, uint32_t r1) {
    asm volatile("stmatrix.sync.aligned.m8n8.x2.shared.b16 [%0], {%1,%2};"
                 :: "r"(a), "r"(r0), "r"(r1) : "memory");
}

#define CP_ASYNC16(dst_smem, src) \
    asm volatile("cp.async.cg.shared.global [%0], [%1], 16;" \
                 :: "r"((unsigned)(dst_smem)), "l"(src))
#define CP_COMMIT()  asm volatile("cp.async.commit_group;")
#define CP_WAIT0()   asm volatile("cp.async.wait_group 0;" ::: "memory")

// ---------------- Kernel 1: fused QKV projection ----------------------------
__global__ __launch_bounds__(256) void qkv_kernel(
    const float* __restrict__ x,
    const float* __restrict__ Wq, const float* __restrict__ bq,
    const float* __restrict__ Wk, const float* __restrict__ bk,
    const float* __restrict__ Wv, const float* __restrict__ bv)
{
    __shared__ float Xs[64 * 64];
    __shared__ float Ws[64 * 68];

    const int p0  = blockIdx.x * 64;
    const int by  = blockIdx.y;
    const int mat = by >> 2;
    const int dl0 = (by & 3) * 64;
    const float* W    = (mat == 0) ? Wq : (mat == 1) ? Wk : Wv;
    const float* bias = (mat == 0) ? bq : (mat == 1) ? bk : bv;

    const int tid = threadIdx.x;
    for (int i = tid; i < 64 * 16; i += 256) {
        int r = i >> 4, c4 = (i & 15) * 4;
        *(float4*)&Xs[r * 64 + c4] = *(const float4*)&x[r * N_POS + p0 + c4];
        *(float4*)&Ws[r * 68 + c4] = *(const float4*)&W[(dl0 + r) * 64 + c4];
    }
    __syncthreads();

    const int tx = tid & 15, ty = tid >> 4;
    float acc[4][4];
#pragma unroll
    for (int i = 0; i < 4; i++)
#pragma unroll
        for (int j = 0; j < 4; j++) acc[i][j] = 0.f;

#pragma unroll 8
    for (int kk = 0; kk < 64; kk++) {
        float a[4];
#pragma unroll
        for (int i = 0; i < 4; i++) a[i] = Ws[(ty * 4 + i) * 68 + kk];
        float4 b = *(const float4*)&Xs[kk * 64 + tx * 4];
#pragma unroll
        for (int i = 0; i < 4; i++) {
            acc[i][0] += a[i] * b.x; acc[i][1] += a[i] * b.y;
            acc[i][2] += a[i] * b.z; acc[i][3] += a[i] * b.w;
        }
    }

#pragma unroll
    for (int i = 0; i < 4; i++) {
        int d = dl0 + ty * 4 + i;
        float bv_ = bias[d];
        int h = d & 7, m = d >> 3;
#pragma unroll
        for (int j = 0; j < 4; j++) {
            int p = p0 + tx * 4 + j;
            float val = acc[i][j] + bv_;
            if (mat == 0)      g_q [(h * N_POS + p) * MIDC + m] = val;
            else if (mat == 1) g_k [(h * N_POS + p) * MIDC + m] = __float2half(val);
            else               g_vT[(h * MIDC + m) * N_POS + p] = __float2half(val);
        }
    }
}

// ---------------- Kernel 2: bias precompute (x INV*LOG2E) -------------------
__global__ __launch_bounds__(256) void bias_kernel(
    const float* __restrict__ rowT, const float* __restrict__ colT)
{
    int idx = blockIdx.x * 256 + threadIdx.x;
    int h   = idx / (N_POS * 112);
    int rem = idx - h * (N_POS * 112);
    int p   = rem / 112;
    int t   = rem - p * 112;
    const float* Qp = &g_q[(h * N_POS + p) * MIDC];
    const float sc = INV * LOG2E;

    if (t < HW) {
        int i = p / HW;
        const float* tr = &rowT[(t - i + 55) * 16];
        float acc = 0.f;
#pragma unroll
        for (int m = 0; m < 16; m++) acc += Qp[m] * tr[m];
        g_rowb[(h * N_POS + p) * HW + t] = acc * sc;
    } else {
        int l = t - HW, j = p % HW;
        const float* tc = &colT[(l - j + 55) * 16];
        float acc = 0.f;
#pragma unroll
        for (int m = 0; m < 16; m++) acc += Qp[16 + m] * tc[m];
        g_colb[(h * N_POS + p) * HW + l] = acc * sc;
    }
}

// ---------------- Kernel 3: fp16 flash attention, ldmatrix/stmatrix ---------
// Block = 128 threads = 4 warps; warp w owns query rows [16w, 16w+16).
// smem layout (bytes):
//   K0 @0      : [56 keys][40 halves] (80B rows)
//   K1 @4480
//   V0 @8960   : [32 ch][72 halves]   (144B rows; V transposed [ch][key])
//   V1 @13568
//   Pm @18176  : [64 q][72 halves]    (144B rows; cols 56..63 zero pad)
//   rb @27392  : [56 kr][64 q] f32
#define KOFF0 0
#define KOFF1 4480
#define VOFF0 8960
#define VOFF1 13568
#define PMOFF 18176
#define RBOFF 27392
#define SMEMB 41728

__global__ __launch_bounds__(128, 3) void attn_kernel()
{
    extern __shared__ char smc[];
    float* smf = (float*)smc;

    const int bx  = blockIdx.x;
    const int h   = bx / 49;
    const int p0  = (bx - h * 49) * 64;
    const int tid = threadIdx.x;
    const int w   = tid >> 5;
    const int ln  = tid & 31;
    const int g   = ln >> 2;          // 0..7
    const int t   = ln & 3;           // 0..3
    const int qr  = ln & 7;           // ldmatrix row-in-group
    const int quad = ln >> 3;         // 0..3
    const int wq0 = w * 16;
    const int hbase = h * N_POS;

    const unsigned sm_u32 = (unsigned)__cvta_generic_to_shared(smc);

    // P base for both STSM and LDSM: row uses quad&1, k-chunk uses quad>>1
    const uint32_t paddr = sm_u32 + PMOFF
        + (uint32_t)(wq0 + 8 * (quad & 1) + qr) * 144 + 16 * (quad >> 1);

    // ---- zero pads: V cols 56..63 (both bufs), P cols 56..63 --------------
    for (int i = tid; i < 256; i += 128) {
        int b = i >> 7, j = i & 127;
        int m = j >> 2, c = j & 3;
        *(uint32_t*)(smc + (b ? VOFF1 : VOFF0) + m * 144 + 112 + c * 4) = 0;
    }
    for (int i = tid; i < 256; i += 128) {
        int q = i >> 2, c = i & 3;
        *(uint32_t*)(smc + PMOFF + q * 144 + 112 + c * 4) = 0;
    }

    // ---- rb tile [kr][q] ---------------------------------------------------
    {
        const float* src = &g_rowb[(hbase + p0) * HW];
        float* rbs = smf + RBOFF / 4;
        for (int i = tid; i < 64 * HW; i += 128) {
            int q = i / HW, kr = i - q * HW;
            rbs[kr * 64 + q] = src[i];
        }
    }

    // ---- Q fragments (x INV*LOG2E) as packed fp16 -------------------------
    uint32_t qa[2][4];
    {
        const float sc = INV * LOG2E;
        const float* Q0 = &g_q[(hbase + p0 + wq0 + g) * MIDC];
        const float* Q8 = Q0 + 8 * MIDC;
#pragma unroll
        for (int kc = 0; kc < 2; kc++) {
            int c0 = 16 * kc + 2 * t;
            qa[kc][0] = pkh2(Q0[c0]     * sc, Q0[c0 + 1] * sc);
            qa[kc][1] = pkh2(Q8[c0]     * sc, Q8[c0 + 1] * sc);
            qa[kc][2] = pkh2(Q0[c0 + 8] * sc, Q0[c0 + 9] * sc);
            qa[kc][3] = pkh2(Q8[c0 + 8] * sc, Q8[c0 + 9] * sc);
        }
    }

    // ---- column-bias registers matching D-fragment layout -----------------
    float cbr[7][4];
    {
        const float* C0 = &g_colb[(hbase + p0 + wq0 + g) * HW];
        const float* C8 = C0 + 8 * HW;
#pragma unroll
        for (int nt = 0; nt < 7; nt++) {
            int c0 = 8 * nt + 2 * t;
            cbr[nt][0] = C0[c0]; cbr[nt][1] = C0[c0 + 1];
            cbr[nt][2] = C8[c0]; cbr[nt][3] = C8[c0 + 1];
        }
    }

    float Oa[4][4];
#pragma unroll
    for (int mt = 0; mt < 4; mt++)
#pragma unroll
        for (int j = 0; j < 4; j++) Oa[mt][j] = 0.f;
    float lsum0 = 0.f, lsum1 = 0.f;

    // ---- async tile loader: K 224x16B + V^T 224x16B -----------------------
    auto load_tile = [&](int kr, int buf) {
        const uint32_t kof = sm_u32 + (buf ? KOFF1 : KOFF0);
        const uint32_t vof = sm_u32 + (buf ? VOFF1 : VOFF0);
        const __half* Kg = g_k  + (hbase + kr * HW) * MIDC;
        const __half* Vg = g_vT + h * MIDC * N_POS + kr * HW;
#pragma unroll 4
        for (int i = tid; i < 448; i += 128) {
            if (i < 224) {
                int l = i >> 2, c = i & 3;
                CP_ASYNC16(kof + l * 80 + c * 16, Kg + l * 32 + c * 8);
            } else {
                int j = i - 224;
                int m = j / 7, t7 = j - m * 7;
                CP_ASYNC16(vof + m * 144 + t7 * 16, Vg + m * N_POS + t7 * 8);
            }
        }
        CP_COMMIT();
    };

    load_tile(0, 0);

    for (int kr = 0; kr < HW; kr++) {
        const int buf = kr & 1;
        CP_WAIT0();
        __syncthreads();
        if (kr + 1 < HW) load_tile(kr + 1, buf ^ 1);

        const uint32_t kof = sm_u32 + (buf ? KOFF1 : KOFF0);
        const uint32_t vof = sm_u32 + (buf ? VOFF1 : VOFF0);

        const float rb0 = smf[RBOFF / 4 + kr * 64 + wq0 + g];
        const float rb1 = smf[RBOFF / 4 + kr * 64 + wq0 + g + 8];

        // ---- S = Q K^T (+bias as C init); P = ex2(S) -> fp16 --------------
        uint32_t pk01[7], pk23[7];
#pragma unroll
        for (int nt = 0; nt < 7; nt++) {
            uint32_t b00, b01, b10, b11;
            ldsm4(b00, b01, b10, b11, kof + (8 * nt + qr) * 80 + 16 * quad);
            float d0 = rb0 + cbr[nt][0];
            float d1 = rb0 + cbr[nt][1];
            float d2 = rb1 + cbr[nt][2];
            float d3 = rb1 + cbr[nt][3];
            mma_f16(d0, d1, d2, d3, qa[0][0], qa[0][1], qa[0][2], qa[0][3], b00, b01);
            mma_f16(d0, d1, d2, d3, qa[1][0], qa[1][1], qa[1][2], qa[1][3], b10, b11);
            float pz0 = ex2f(d0), pz1 = ex2f(d1), pz2 = ex2f(d2), pz3 = ex2f(d3);
            lsum0 += pz0 + pz1;
            lsum1 += pz2 + pz3;
            pk01[nt] = pkh2(pz0, pz1);
            pk23[nt] = pkh2(pz2, pz3);
        }
        stsm4(paddr,      pk01[0], pk23[0], pk01[1], pk23[1]);
        stsm4(paddr + 32, pk01[2], pk23[2], pk01[3], pk23[3]);
        stsm4(paddr + 64, pk01[4], pk23[4], pk01[5], pk23[5]);
        stsm2(paddr + 96, pk01[6], pk23[6]);

        __syncwarp();

        // ---- O += P V  (ldmatrix fragments) -------------------------------
#pragma unroll
        for (int kc = 0; kc < 4; kc++) {
            uint32_t a0, a1, a2, a3;
            ldsm4(a0, a1, a2, a3, paddr + kc * 32);
            uint32_t v00, v01, v10, v11, v20, v21, v30, v31;
            const uint32_t vrow = vof + (8 * (quad >> 1) + qr) * 144
                                + kc * 32 + 16 * (quad & 1);
            ldsm4(v00, v01, v10, v11, vrow);
            ldsm4(v20, v21, v30, v31, vrow + 16 * 144);
            mma_f16(Oa[0][0], Oa[0][1], Oa[0][2], Oa[0][3], a0, a1, a2, a3, v00, v01);
            mma_f16(Oa[1][0], Oa[1][1], Oa[1][2], Oa[1][3], a0, a1, a2, a3, v10, v11);
            mma_f16(Oa[2][0], Oa[2][1], Oa[2][2], Oa[2][3], a0, a1, a2, a3, v20, v21);
            mma_f16(Oa[3][0], Oa[3][1], Oa[3][2], Oa[3][3], a0, a1, a2, a3, v30, v31);
        }
    }

    // ---- normalize + store -------------------------------------------------
    lsum0 += __shfl_xor_sync(0xffffffffu, lsum0, 1);
    lsum0 += __shfl_xor_sync(0xffffffffu, lsum0, 2);
    lsum1 += __shfl_xor_sync(0xffffffffu, lsum1, 1);
    lsum1 += __shfl_xor_sync(0xffffffffu, lsum1, 2);
    const float rinv0 = 1.0f / lsum0;
    const float rinv1 = 1.0f / lsum1;

    const int pA = p0 + wq0 + g;
#pragma unroll
    for (int mt = 0; mt < 4; mt++) {
        int c0 = 8 * mt + 2 * t;
        g_o[(c0       * HEADS + h) * N_POS + pA]     = Oa[mt][0] * rinv0;
        g_o[((c0 + 1) * HEADS + h) * N_POS + pA]     = Oa[mt][1] * rinv0;
        g_o[(c0       * HEADS + h) * N_POS + pA + 8] = Oa[mt][2] * rinv1;
        g_o[((c0 + 1) * HEADS + h) * N_POS + pA + 8] = Oa[mt][3] * rinv1;
    }
}

// ---------------- Kernel 4: output projection -------------------------------
__global__ __launch_bounds__(256) void out_kernel(
    const float* __restrict__ Wo, const float* __restrict__ bo,
    float* __restrict__ out)
{
    __shared__ float Xs[64 * 64];
    __shared__ float Ws[16 * 68];

    const int p0  = blockIdx.x * 64;
    const int co0 = blockIdx.y * 16;
    const int tid = threadIdx.x;
    const int tx = tid & 15, ty = tid >> 4;
    float acc[4] = {0.f, 0.f, 0.f, 0.f};

    for (int kc = 0; kc < 256; kc += 64) {
        __syncthreads();
        for (int i = tid; i < 64 * 16; i += 256) {
            int r = i >> 4, c4 = (i & 15) * 4;
            *(float4*)&Xs[r * 64 + c4] = *(const float4*)&g_o[(kc + r) * N_POS + p0 + c4];
        }
        {
            int r = tid >> 4, c4 = (tid & 15) * 4;
            *(float4*)&Ws[r * 68 + c4] = *(const float4*)&Wo[(co0 + r) * 256 + kc + c4];
        }
        __syncthreads();
#pragma unroll 8
        for (int kk = 0; kk < 64; kk++) {
            float a = Ws[ty * 68 + kk];
            float4 b = *(const float4*)&Xs[kk * 64 + tx * 4];
            acc[0] += a * b.x; acc[1] += a * b.y; acc[2] += a * b.z; acc[3] += a * b.w;
        }
    }
    float bv_ = bo[co0 + ty];
#pragma unroll
    for (int j = 0; j < 4; j++)
        out[(co0 + ty) * N_POS + p0 + tx * 4 + j] = acc[j] + bv_;
}

// ---------------- launch -----------------------------------------------------
extern "C" void kernel_launch(void* const* d_in, const int* in_sizes, int n_in,
                              void* d_out, int out_size)
{
    const float* x    = (const float*)d_in[0];
    const float* Wq   = (const float*)d_in[1];
    const float* bq   = (const float*)d_in[2];
    const float* Wk   = (const float*)d_in[3];
    const float* bk   = (const float*)d_in[4];
    const float* Wv   = (const float*)d_in[5];
    const float* bv   = (const float*)d_in[6];
    const float* Wo   = (const float*)d_in[7];
    const float* bo   = (const float*)d_in[8];
    const float* rowT = (const float*)d_in[9];
    const float* colT = (const float*)d_in[10];

    cudaFuncSetAttribute(attn_kernel,
                         cudaFuncAttributeMaxDynamicSharedMemorySize, SMEMB);

    qkv_kernel<<<dim3(49, 12), 256>>>(x, Wq, bq, Wk, bk, Wv, bv);
    bias_kernel<<<10976, 256>>>(rowT, colT);
    attn_kernel<<<392, 128, SMEMB>>>();
    out_kernel<<<dim3(49, 4), 256>>>(Wo, bo, (float*)d_out);
}

// round 10
// speedup vs baseline: 1.4968x; 1.4968x over previous
#include <cuda_runtime.h>
#include <cuda_fp16.h>
#include <math_constants.h>
#include <cstdint>

#define N_POS 3136
#define HW    56
#define MIDC  32
#define HEADS 8
#define INV   0.125f   // 1/sqrt(64)
#define LOG2E 1.4426950408889634f

// ---------------- scratch (global, no allocation in kernel_launch) ----------
__device__ float  g_q [HEADS * N_POS * MIDC];   // [h][p][m] fp32 (bias kernel reads)
__device__ __half g_k [HEADS * N_POS * MIDC];   // [h][p][m] fp16
__device__ __half g_vT[HEADS * MIDC * N_POS];   // [h][m][p] fp16 (transposed V)
__device__ float g_rowb[HEADS * N_POS * HW];    // log2e*inv-scaled row bias
__device__ float g_colb[HEADS * N_POS * HW];    // log2e*inv-scaled col bias
__device__ float g_o[MIDC * HEADS * N_POS];     // [channel = m*8+h][p]

// ---------------- helpers ----------------------------------------------------
__device__ __forceinline__ uint32_t pkh2(float lo, float hi) {
    uint32_t r;
    asm("cvt.rn.f16x2.f32 %0, %1, %2;" : "=r"(r) : "f"(hi), "f"(lo));
    return r;
}
__device__ __forceinline__ float ex2f(float x) {
    float r; asm("ex2.approx.ftz.f32 %0, %1;" : "=f"(r) : "f"(x)); return r;
}
__device__ __forceinline__ void mma_f16(
    float& d0, float& d1, float& d2, float& d3,
    uint32_t a0, uint32_t a1, uint32_t a2, uint32_t a3,
    uint32_t b0, uint32_t b1)
{
    asm("mma.sync.aligned.m16n8k16.row.col.f32.f16.f16.f32 "
        "{%0,%1,%2,%3}, {%4,%5,%6,%7}, {%8,%9}, {%0,%1,%2,%3};"
        : "+f"(d0), "+f"(d1), "+f"(d2), "+f"(d3)
        : "r"(a0), "r"(a1), "r"(a2), "r"(a3), "r"(b0), "r"(b1));
}

#define CP_ASYNC16(dst_smem, src) \
    asm volatile("cp.async.cg.shared.global [%0], [%1], 16;" \
                 :: "r"((unsigned)(dst_smem)), "l"(src))
#define CP_COMMIT()  asm volatile("cp.async.commit_group;")
#define CP_WAIT0()   asm volatile("cp.async.wait_group 0;" ::: "memory")

// ---------------- Kernel 1: fused QKV projection ----------------------------
__global__ __launch_bounds__(256) void qkv_kernel(
    const float* __restrict__ x,
    const float* __restrict__ Wq, const float* __restrict__ bq,
    const float* __restrict__ Wk, const float* __restrict__ bk,
    const float* __restrict__ Wv, const float* __restrict__ bv)
{
    __shared__ float Xs[64 * 64];
    __shared__ float Ws[64 * 68];

    const int p0  = blockIdx.x * 64;
    const int by  = blockIdx.y;
    const int mat = by >> 2;
    const int dl0 = (by & 3) * 64;
    const float* W    = (mat == 0) ? Wq : (mat == 1) ? Wk : Wv;
    const float* bias = (mat == 0) ? bq : (mat == 1) ? bk : bv;

    const int tid = threadIdx.x;
    for (int i = tid; i < 64 * 16; i += 256) {
        int r = i >> 4, c4 = (i & 15) * 4;
        *(float4*)&Xs[r * 64 + c4] = *(const float4*)&x[r * N_POS + p0 + c4];
        *(float4*)&Ws[r * 68 + c4] = *(const float4*)&W[(dl0 + r) * 64 + c4];
    }
    __syncthreads();

    const int tx = tid & 15, ty = tid >> 4;
    float acc[4][4];
#pragma unroll
    for (int i = 0; i < 4; i++)
#pragma unroll
        for (int j = 0; j < 4; j++) acc[i][j] = 0.f;

#pragma unroll 8
    for (int kk = 0; kk < 64; kk++) {
        float a[4];
#pragma unroll
        for (int i = 0; i < 4; i++) a[i] = Ws[(ty * 4 + i) * 68 + kk];
        float4 b = *(const float4*)&Xs[kk * 64 + tx * 4];
#pragma unroll
        for (int i = 0; i < 4; i++) {
            acc[i][0] += a[i] * b.x; acc[i][1] += a[i] * b.y;
            acc[i][2] += a[i] * b.z; acc[i][3] += a[i] * b.w;
        }
    }

#pragma unroll
    for (int i = 0; i < 4; i++) {
        int d = dl0 + ty * 4 + i;
        float bv_ = bias[d];
        int h = d & 7, m = d >> 3;
#pragma unroll
        for (int j = 0; j < 4; j++) {
            int p = p0 + tx * 4 + j;
            float val = acc[i][j] + bv_;
            if (mat == 0)      g_q [(h * N_POS + p) * MIDC + m] = val;
            else if (mat == 1) g_k [(h * N_POS + p) * MIDC + m] = __float2half(val);
            else               g_vT[(h * MIDC + m) * N_POS + p] = __float2half(val);
        }
    }
}

// ---------------- Kernel 2: bias precompute (x INV*LOG2E) -------------------
__global__ __launch_bounds__(256) void bias_kernel(
    const float* __restrict__ rowT, const float* __restrict__ colT)
{
    int idx = blockIdx.x * 256 + threadIdx.x;
    int h   = idx / (N_POS * 112);
    int rem = idx - h * (N_POS * 112);
    int p   = rem / 112;
    int t   = rem - p * 112;
    const float* Qp = &g_q[(h * N_POS + p) * MIDC];
    const float sc = INV * LOG2E;

    if (t < HW) {
        int i = p / HW;
        const float* tr = &rowT[(t - i + 55) * 16];
        float acc = 0.f;
#pragma unroll
        for (int m = 0; m < 16; m++) acc += Qp[m] * tr[m];
        g_rowb[(h * N_POS + p) * HW + t] = acc * sc;
    } else {
        int l = t - HW, j = p % HW;
        const float* tc = &colT[(l - j + 55) * 16];
        float acc = 0.f;
#pragma unroll
        for (int m = 0; m < 16; m++) acc += Qp[16 + m] * tc[m];
        g_colb[(h * N_POS + p) * HW + l] = acc * sc;
    }
}

// ---------------- Kernel 3: fp16 m16n8k16 flash attention (R8 layout) -------
// Block = 128 threads = 4 warps; warp w owns query rows [16w, 16w+16).
// smem layout (bytes):
//   K0 @0      : [56 keys][40 halves]   (80B rows, 20 words, conflict-free)
//   K1 @4480
//   V0 @8960   : [32 ch][72 halves]     (144B rows; V transposed [ch][key])
//   V1 @13568
//   Pm @18176  : [64 q][72 halves]      (cols 56..63 zero pad)
//   rb @27392  : [56 kr][64 q] f32
#define KOFF0 0
#define KOFF1 4480
#define VOFF0 8960
#define VOFF1 13568
#define PMOFF 18176
#define RBOFF 27392
#define SMEMB 41728

__global__ __launch_bounds__(128, 3) void attn_kernel()
{
    extern __shared__ char smc[];
    float* smf = (float*)smc;

    const int bx  = blockIdx.x;
    const int h   = bx / 49;
    const int p0  = (bx - h * 49) * 64;
    const int tid = threadIdx.x;
    const int w   = tid >> 5;
    const int ln  = tid & 31;
    const int g   = ln >> 2;          // 0..7
    const int t   = ln & 3;           // 0..3
    const int wq0 = w * 16;
    const int hbase = h * N_POS;

    const unsigned sm_u32 = (unsigned)__cvta_generic_to_shared(smc);

    // ---- zero pads: V cols 56..63 (both bufs), P cols 56..63 --------------
    for (int i = tid; i < 256; i += 128) {
        int b = i >> 7, j = i & 127;
        int m = j >> 2, c = j & 3;
        *(uint32_t*)(smc + (b ? VOFF1 : VOFF0) + m * 144 + 112 + c * 4) = 0;
    }
    for (int i = tid; i < 256; i += 128) {
        int q = i >> 2, c = i & 3;
        *(uint32_t*)(smc + PMOFF + q * 144 + 112 + c * 4) = 0;
    }

    // ---- rb tile [kr][q] ---------------------------------------------------
    {
        const float* src = &g_rowb[(hbase + p0) * HW];
        float* rbs = smf + RBOFF / 4;
        for (int i = tid; i < 64 * HW; i += 128) {
            int q = i / HW, kr = i - q * HW;
            rbs[kr * 64 + q] = src[i];
        }
    }

    // ---- Q fragments (x INV*LOG2E) as packed fp16 -------------------------
    uint32_t qa[2][4];
    {
        const float sc = INV * LOG2E;
        const float* Q0 = &g_q[(hbase + p0 + wq0 + g) * MIDC];
        const float* Q8 = Q0 + 8 * MIDC;
#pragma unroll
        for (int kc = 0; kc < 2; kc++) {
            int c0 = 16 * kc + 2 * t;
            qa[kc][0] = pkh2(Q0[c0]     * sc, Q0[c0 + 1] * sc);
            qa[kc][1] = pkh2(Q8[c0]     * sc, Q8[c0 + 1] * sc);
            qa[kc][2] = pkh2(Q0[c0 + 8] * sc, Q0[c0 + 9] * sc);
            qa[kc][3] = pkh2(Q8[c0 + 8] * sc, Q8[c0 + 9] * sc);
        }
    }

    // ---- column-bias registers matching D-fragment layout -----------------
    float cbr[7][4];
    {
        const float* C0 = &g_colb[(hbase + p0 + wq0 + g) * HW];
        const float* C8 = C0 + 8 * HW;
#pragma unroll
        for (int nt = 0; nt < 7; nt++) {
            int c0 = 8 * nt + 2 * t;
            cbr[nt][0] = C0[c0]; cbr[nt][1] = C0[c0 + 1];
            cbr[nt][2] = C8[c0]; cbr[nt][3] = C8[c0 + 1];
        }
    }

    float Oa[4][4];
#pragma unroll
    for (int mt = 0; mt < 4; mt++)
#pragma unroll
        for (int j = 0; j < 4; j++) Oa[mt][j] = 0.f;
    float lsum0 = 0.f, lsum1 = 0.f;

    // ---- async tile loader: K 224x16B + V^T 224x16B -----------------------
    auto load_tile = [&](int kr, int buf) {
        const uint32_t kof = sm_u32 + (buf ? KOFF1 : KOFF0);
        const uint32_t vof = sm_u32 + (buf ? VOFF1 : VOFF0);
        const __half* Kg = g_k  + (hbase + kr * HW) * MIDC;
        const __half* Vg = g_vT + h * MIDC * N_POS + kr * HW;
#pragma unroll 4
        for (int i = tid; i < 448; i += 128) {
            if (i < 224) {
                int l = i >> 2, c = i & 3;
                CP_ASYNC16(kof + l * 80 + c * 16, Kg + l * 32 + c * 8);
            } else {
                int j = i - 224;
                int m = j / 7, t7 = j - m * 7;
                CP_ASYNC16(vof + m * 144 + t7 * 16, Vg + m * N_POS + t7 * 8);
            }
        }
        CP_COMMIT();
    };

    load_tile(0, 0);

    for (int kr = 0; kr < HW; kr++) {
        const int buf = kr & 1;
        CP_WAIT0();
        __syncthreads();
        if (kr + 1 < HW) load_tile(kr + 1, buf ^ 1);

        const uint32_t* Ku = (const uint32_t*)(smc + (buf ? KOFF1 : KOFF0));
        const uint32_t* Vw = (const uint32_t*)(smc + (buf ? VOFF1 : VOFF0));
        uint32_t* Pw = (uint32_t*)(smc + PMOFF);

        const float rb0 = smf[RBOFF / 4 + kr * 64 + wq0 + g];
        const float rb1 = smf[RBOFF / 4 + kr * 64 + wq0 + g + 8];

        // ---- S = Q K^T (+bias as C init); P = ex2(S) -> fp16 --------------
#pragma unroll
        for (int nt = 0; nt < 7; nt++) {
            const int l0 = 8 * nt;
            const uint32_t* krow = Ku + (l0 + g) * 20 + t;
            uint32_t b00 = krow[0], b01 = krow[4], b10 = krow[8], b11 = krow[12];
            float d0 = rb0 + cbr[nt][0];
            float d1 = rb0 + cbr[nt][1];
            float d2 = rb1 + cbr[nt][2];
            float d3 = rb1 + cbr[nt][3];
            mma_f16(d0, d1, d2, d3, qa[0][0], qa[0][1], qa[0][2], qa[0][3], b00, b01);
            mma_f16(d0, d1, d2, d3, qa[1][0], qa[1][1], qa[1][2], qa[1][3], b10, b11);

            float pz0 = ex2f(d0), pz1 = ex2f(d1), pz2 = ex2f(d2), pz3 = ex2f(d3);
            lsum0 += pz0 + pz1;
            lsum1 += pz2 + pz3;
            Pw[(wq0 + g)     * 36 + 4 * nt + t] = pkh2(pz0, pz1);
            Pw[(wq0 + g + 8) * 36 + 4 * nt + t] = pkh2(pz2, pz3);
        }

        __syncwarp();

        // ---- O += P V  (4 k16 chunks over 64 padded keys) -----------------
#pragma unroll
        for (int kc = 0; kc < 4; kc++) {
            const uint32_t* pr0 = Pw + (wq0 + g)     * 36 + 8 * kc + t;
            const uint32_t* pr8 = Pw + (wq0 + g + 8) * 36 + 8 * kc + t;
            uint32_t a0 = pr0[0], a1 = pr8[0], a2 = pr0[4], a3 = pr8[4];
#pragma unroll
            for (int mt = 0; mt < 4; mt++) {
                const uint32_t* vrow = Vw + (8 * mt + g) * 36 + 8 * kc + t;
                mma_f16(Oa[mt][0], Oa[mt][1], Oa[mt][2], Oa[mt][3],
                        a0, a1, a2, a3, vrow[0], vrow[4]);
            }
        }
    }

    // ---- normalize + store -------------------------------------------------
    lsum0 += __shfl_xor_sync(0xffffffffu, lsum0, 1);
    lsum0 += __shfl_xor_sync(0xffffffffu, lsum0, 2);
    lsum1 += __shfl_xor_sync(0xffffffffu, lsum1, 1);
    lsum1 += __shfl_xor_sync(0xffffffffu, lsum1, 2);
    const float rinv0 = 1.0f / lsum0;
    const float rinv1 = 1.0f / lsum1;

    const int pA = p0 + wq0 + g;
#pragma unroll
    for (int mt = 0; mt < 4; mt++) {
        int c0 = 8 * mt + 2 * t;
        g_o[(c0       * HEADS + h) * N_POS + pA]     = Oa[mt][0] * rinv0;
        g_o[((c0 + 1) * HEADS + h) * N_POS + pA]     = Oa[mt][1] * rinv0;
        g_o[(c0       * HEADS + h) * N_POS + pA + 8] = Oa[mt][2] * rinv1;
        g_o[((c0 + 1) * HEADS + h) * N_POS + pA + 8] = Oa[mt][3] * rinv1;
    }
}

// ---------------- Kernel 4: output projection -------------------------------
__global__ __launch_bounds__(256) void out_kernel(
    const float* __restrict__ Wo, const float* __restrict__ bo,
    float* __restrict__ out)
{
    __shared__ float Xs[64 * 64];
    __shared__ float Ws[16 * 68];

    const int p0  = blockIdx.x * 64;
    const int co0 = blockIdx.y * 16;
    const int tid = threadIdx.x;
    const int tx = tid & 15, ty = tid >> 4;
    float acc[4] = {0.f, 0.f, 0.f, 0.f};

    for (int kc = 0; kc < 256; kc += 64) {
        __syncthreads();
        for (int i = tid; i < 64 * 16; i += 256) {
            int r = i >> 4, c4 = (i & 15) * 4;
            *(float4*)&Xs[r * 64 + c4] = *(const float4*)&g_o[(kc + r) * N_POS + p0 + c4];
        }
        {
            int r = tid >> 4, c4 = (tid & 15) * 4;
            *(float4*)&Ws[r * 68 + c4] = *(const float4*)&Wo[(co0 + r) * 256 + kc + c4];
        }
        __syncthreads();
#pragma unroll 8
        for (int kk = 0; kk < 64; kk++) {
            float a = Ws[ty * 68 + kk];
            float4 b = *(const float4*)&Xs[kk * 64 + tx * 4];
            acc[0] += a * b.x; acc[1] += a * b.y; acc[2] += a * b.z; acc[3] += a * b.w;
        }
    }
    float bv_ = bo[co0 + ty];
#pragma unroll
    for (int j = 0; j < 4; j++)
        out[(co0 + ty) * N_POS + p0 + tx * 4 + j] = acc[j] + bv_;
}

// ---------------- launch -----------------------------------------------------
extern "C" void kernel_launch(void* const* d_in, const int* in_sizes, int n_in,
                              void* d_out, int out_size)
{
    const float* x    = (const float*)d_in[0];
    const float* Wq   = (const float*)d_in[1];
    const float* bq   = (const float*)d_in[2];
    const float* Wk   = (const float*)d_in[3];
    const float* bk   = (const float*)d_in[4];
    const float* Wv   = (const float*)d_in[5];
    const float* bv   = (const float*)d_in[6];
    const float* Wo   = (const float*)d_in[7];
    const float* bo   = (const float*)d_in[8];
    const float* rowT = (const float*)d_in[9];
    const float* colT = (const float*)d_in[10];

    cudaFuncSetAttribute(attn_kernel,
                         cudaFuncAttributeMaxDynamicSharedMemorySize, SMEMB);

    qkv_kernel<<<dim3(49, 12), 256>>>(x, Wq, bq, Wk, bk, Wv, bv);
    bias_kernel<<<10976, 256>>>(rowT, colT);
    attn_kernel<<<392, 128, SMEMB>>>();
    out_kernel<<<dim3(49, 4), 256>>>(Wo, bo, (float*)d_out);
}

// round 11
// speedup vs baseline: 1.5134x; 1.0111x over previous
#include <cuda_runtime.h>
#include <cuda_fp16.h>
#include <math_constants.h>
#include <cstdint>

#define N_POS 3136
#define HW    56
#define MIDC  32
#define HEADS 8
#define INV   0.125f   // 1/sqrt(64)
#define LOG2E 1.4426950408889634f
#define NITER 28       // 3136 / 112 key-chunks

// ---------------- scratch (global, no allocation in kernel_launch) ----------
__device__ float  g_q [HEADS * N_POS * MIDC];   // [h][p][m] fp32
__device__ __half g_k [HEADS * N_POS * MIDC];   // [h][p][m] fp16
__device__ __half g_vT[HEADS * MIDC * N_POS];   // [h][m][p] fp16 (transposed V)
__device__ __half g_rowb[HEADS * N_POS * HW];   // log2e*inv-scaled row bias (f16)
__device__ __half g_colb[HEADS * N_POS * HW];   // log2e*inv-scaled col bias (f16)
__device__ float g_o[MIDC * HEADS * N_POS];     // [channel = m*8+h][p]

// ---------------- helpers ----------------------------------------------------
__device__ __forceinline__ uint32_t pkh2(float lo, float hi) {
    uint32_t r;
    asm("cvt.rn.f16x2.f32 %0, %1, %2;" : "=r"(r) : "f"(hi), "f"(lo));
    return r;
}
__device__ __forceinline__ uint32_t ex2h2(uint32_t x) {
    uint32_t r; asm("ex2.approx.f16x2 %0, %1;" : "=r"(r) : "r"(x)); return r;
}
__device__ __forceinline__ uint32_t haddu2(uint32_t a, uint32_t b) {
    uint32_t r; asm("add.rn.f16x2 %0, %1, %2;" : "=r"(r) : "r"(a), "r"(b)); return r;
}
// f32-accumulator MMA (PV)
__device__ __forceinline__ void mma_f16(
    float& d0, float& d1, float& d2, float& d3,
    uint32_t a0, uint32_t a1, uint32_t a2, uint32_t a3,
    uint32_t b0, uint32_t b1)
{
    asm("mma.sync.aligned.m16n8k16.row.col.f32.f16.f16.f32 "
        "{%0,%1,%2,%3}, {%4,%5,%6,%7}, {%8,%9}, {%0,%1,%2,%3};"
        : "+f"(d0), "+f"(d1), "+f"(d2), "+f"(d3)
        : "r"(a0), "r"(a1), "r"(a2), "r"(a3), "r"(b0), "r"(b1));
}
// f16-accumulator MMA (S): D/C are 2 x f16x2
__device__ __forceinline__ void mma_f16acc(
    uint32_t& d0, uint32_t& d1,
    uint32_t a0, uint32_t a1, uint32_t a2, uint32_t a3,
    uint32_t b0, uint32_t b1)
{
    asm("mma.sync.aligned.m16n8k16.row.col.f16.f16.f16.f16 "
        "{%0,%1}, {%2,%3,%4,%5}, {%6,%7}, {%0,%1};"
        : "+r"(d0), "+r"(d1)
        : "r"(a0), "r"(a1), "r"(a2), "r"(a3), "r"(b0), "r"(b1));
}

#define CP_ASYNC16(dst_smem, src) \
    asm volatile("cp.async.cg.shared.global [%0], [%1], 16;" \
                 :: "r"((unsigned)(dst_smem)), "l"(src))
#define CP_COMMIT()  asm volatile("cp.async.commit_group;")
#define CP_WAIT0()   asm volatile("cp.async.wait_group 0;" ::: "memory")

// ---------------- Kernel 1: fused QKV projection ----------------------------
__global__ __launch_bounds__(256) void qkv_kernel(
    const float* __restrict__ x,
    const float* __restrict__ Wq, const float* __restrict__ bq,
    const float* __restrict__ Wk, const float* __restrict__ bk,
    const float* __restrict__ Wv, const float* __restrict__ bv)
{
    __shared__ float Xs[64 * 64];
    __shared__ float Ws[64 * 68];

    const int p0  = blockIdx.x * 64;
    const int by  = blockIdx.y;
    const int mat = by >> 2;
    const int dl0 = (by & 3) * 64;
    const float* W    = (mat == 0) ? Wq : (mat == 1) ? Wk : Wv;
    const float* bias = (mat == 0) ? bq : (mat == 1) ? bk : bv;

    const int tid = threadIdx.x;
    for (int i = tid; i < 64 * 16; i += 256) {
        int r = i >> 4, c4 = (i & 15) * 4;
        *(float4*)&Xs[r * 64 + c4] = *(const float4*)&x[r * N_POS + p0 + c4];
        *(float4*)&Ws[r * 68 + c4] = *(const float4*)&W[(dl0 + r) * 64 + c4];
    }
    __syncthreads();

    const int tx = tid & 15, ty = tid >> 4;
    float acc[4][4];
#pragma unroll
    for (int i = 0; i < 4; i++)
#pragma unroll
        for (int j = 0; j < 4; j++) acc[i][j] = 0.f;

#pragma unroll 8
    for (int kk = 0; kk < 64; kk++) {
        float a[4];
#pragma unroll
        for (int i = 0; i < 4; i++) a[i] = Ws[(ty * 4 + i) * 68 + kk];
        float4 b = *(const float4*)&Xs[kk * 64 + tx * 4];
#pragma unroll
        for (int i = 0; i < 4; i++) {
            acc[i][0] += a[i] * b.x; acc[i][1] += a[i] * b.y;
            acc[i][2] += a[i] * b.z; acc[i][3] += a[i] * b.w;
        }
    }

#pragma unroll
    for (int i = 0; i < 4; i++) {
        int d = dl0 + ty * 4 + i;
        float bv_ = bias[d];
        int h = d & 7, m = d >> 3;
#pragma unroll
        for (int j = 0; j < 4; j++) {
            int p = p0 + tx * 4 + j;
            float val = acc[i][j] + bv_;
            if (mat == 0)      g_q [(h * N_POS + p) * MIDC + m] = val;
            else if (mat == 1) g_k [(h * N_POS + p) * MIDC + m] = __float2half(val);
            else               g_vT[(h * MIDC + m) * N_POS + p] = __float2half(val);
        }
    }
}

// ---------------- Kernel 2: bias precompute (x INV*LOG2E, f16 out) ----------
__global__ __launch_bounds__(256) void bias_kernel(
    const float* __restrict__ rowT, const float* __restrict__ colT)
{
    int idx = blockIdx.x * 256 + threadIdx.x;
    int h   = idx / (N_POS * 112);
    int rem = idx - h * (N_POS * 112);
    int p   = rem / 112;
    int t   = rem - p * 112;
    const float* Qp = &g_q[(h * N_POS + p) * MIDC];
    const float sc = INV * LOG2E;

    if (t < HW) {
        int i = p / HW;
        const float* tr = &rowT[(t - i + 55) * 16];
        float acc = 0.f;
#pragma unroll
        for (int m = 0; m < 16; m++) acc += Qp[m] * tr[m];
        g_rowb[(h * N_POS + p) * HW + t] = __float2half(acc * sc);
    } else {
        int l = t - HW, j = p % HW;
        const float* tc = &colT[(l - j + 55) * 16];
        float acc = 0.f;
#pragma unroll
        for (int m = 0; m < 16; m++) acc += Qp[16 + m] * tc[m];
        g_colb[(h * N_POS + p) * HW + l] = __float2half(acc * sc);
    }
}

// ---------------- Kernel 3: fp16 flash attention, 112-key iterations --------
// Block = 128 threads = 4 warps; warp w owns query rows [16w, 16w+16).
// smem (bytes):
//   K0 @0      : [112 keys][40 halves] (80B rows, 20-word stride)
//   K1 @8960
//   V0 @17920  : [32 ch][136 halves]   (272B rows, 68-word stride)
//   V1 @26624
//   Pm @35328  : [64 q][136 halves]    (68-word stride)
//   rb @52736  : [56 kr][64 q] f16
#define KOFF0 0
#define KOFF1 8960
#define VOFF0 17920
#define VOFF1 26624
#define PMOFF 35328
#define RBOFF 52736
#define SMEMB 59904

__global__ __launch_bounds__(128, 3) void attn_kernel()
{
    extern __shared__ char smc[];

    const int bx  = blockIdx.x;
    const int h   = bx / 49;
    const int p0  = (bx - h * 49) * 64;
    const int tid = threadIdx.x;
    const int w   = tid >> 5;
    const int ln  = tid & 31;
    const int g   = ln >> 2;          // 0..7
    const int t   = ln & 3;           // 0..3
    const int wq0 = w * 16;
    const int hbase = h * N_POS;

    const unsigned sm_u32 = (unsigned)__cvta_generic_to_shared(smc);
    __half* rbs = (__half*)(smc + RBOFF);

    // ---- rb tile [kr][q] (f16, transposed from g_rowb[p][kr]) -------------
    {
        const __half* src = &g_rowb[(hbase + p0) * HW];
        for (int i = tid; i < 64 * HW; i += 128) {
            int q = i / HW, kr = i - q * HW;
            rbs[kr * 64 + q] = src[i];
        }
    }

    // ---- Q fragments (x INV*LOG2E) as packed fp16 -------------------------
    uint32_t qa[2][4];
    {
        const float sc = INV * LOG2E;
        const float* Q0 = &g_q[(hbase + p0 + wq0 + g) * MIDC];
        const float* Q8 = Q0 + 8 * MIDC;
#pragma unroll
        for (int kc = 0; kc < 2; kc++) {
            int c0 = 16 * kc + 2 * t;
            qa[kc][0] = pkh2(Q0[c0]     * sc, Q0[c0 + 1] * sc);
            qa[kc][1] = pkh2(Q8[c0]     * sc, Q8[c0 + 1] * sc);
            qa[kc][2] = pkh2(Q0[c0 + 8] * sc, Q0[c0 + 9] * sc);
            qa[kc][3] = pkh2(Q8[c0 + 8] * sc, Q8[c0 + 9] * sc);
        }
    }

    // ---- column-bias as packed f16x2 pairs (rows g and g+8) ---------------
    uint32_t cb2g[7], cb2g8[7];
    {
        const __half* C0 = &g_colb[(hbase + p0 + wq0 + g) * HW];
        const __half* C8 = C0 + 8 * HW;
#pragma unroll
        for (int nt = 0; nt < 7; nt++) {
            int c0 = 8 * nt + 2 * t;
            cb2g[nt]  = *(const uint32_t*)(C0 + c0);
            cb2g8[nt] = *(const uint32_t*)(C8 + c0);
        }
    }

    float Oa[4][4];
#pragma unroll
    for (int mt = 0; mt < 4; mt++)
#pragma unroll
        for (int j = 0; j < 4; j++) Oa[mt][j] = 0.f;
    float lsum0 = 0.f, lsum1 = 0.f;

    // ---- async tile loader: K 448x16B + V^T 448x16B -----------------------
    auto load_tile = [&](int c, int buf) {
        const uint32_t kof = sm_u32 + (buf ? KOFF1 : KOFF0);
        const uint32_t vof = sm_u32 + (buf ? VOFF1 : VOFF0);
        const __half* Kg = g_k  + (hbase + c * 112) * MIDC;
        const __half* Vg = g_vT + h * MIDC * N_POS + c * 112;
#pragma unroll 7
        for (int i = tid; i < 896; i += 128) {
            if (i < 448) {
                int r = i >> 2, cc = i & 3;
                CP_ASYNC16(kof + r * 80 + cc * 16, Kg + r * 32 + cc * 8);
            } else {
                int j = i - 448;
                int m = j / 14, t14 = j - m * 14;
                CP_ASYNC16(vof + m * 272 + t14 * 16, Vg + m * N_POS + t14 * 8);
            }
        }
        CP_COMMIT();
    };

    load_tile(0, 0);

    for (int c = 0; c < NITER; c++) {
        const int buf = c & 1;
        CP_WAIT0();
        __syncthreads();
        if (c + 1 < NITER) load_tile(c + 1, buf ^ 1);

        const uint32_t* Ku = (const uint32_t*)(smc + (buf ? KOFF1 : KOFF0));
        const uint32_t* Vw = (const uint32_t*)(smc + (buf ? VOFF1 : VOFF0));
        uint32_t* Pw = (uint32_t*)(smc + PMOFF);

        // rb broadcast pairs for the two key-rows of this chunk
        const int kr0 = 2 * c;
        uint32_t r2[2][2];      // [keyrow][qrow 0/8]
#pragma unroll
        for (int kk = 0; kk < 2; kk++) {
            __half ha = rbs[(kr0 + kk) * 64 + wq0 + g];
            __half hb = rbs[(kr0 + kk) * 64 + wq0 + g + 8];
            __half2 pa = __half2half2(ha), pb = __half2half2(hb);
            r2[kk][0] = *(uint32_t*)&pa;
            r2[kk][1] = *(uint32_t*)&pb;
        }

        uint32_t ls2g = 0u, ls2g8 = 0u;   // f16x2 zero

        // ---- S = Q K^T (f16 acc, bias as C); P = ex2.f16x2 ---------------
#pragma unroll
        for (int nt = 0; nt < 14; nt++) {
            const int sel = (nt < 7) ? 0 : 1;
            const int ci  = (nt < 7) ? nt : nt - 7;
            const uint32_t* krow = Ku + (8 * nt + g) * 20 + t;
            uint32_t b00 = krow[0], b01 = krow[4], b10 = krow[8], b11 = krow[12];
            uint32_t d0 = haddu2(r2[sel][0], cb2g[ci]);
            uint32_t d1 = haddu2(r2[sel][1], cb2g8[ci]);
            mma_f16acc(d0, d1, qa[0][0], qa[0][1], qa[0][2], qa[0][3], b00, b01);
            mma_f16acc(d0, d1, qa[1][0], qa[1][1], qa[1][2], qa[1][3], b10, b11);
            uint32_t e0 = ex2h2(d0);
            uint32_t e1 = ex2h2(d1);
            ls2g  = haddu2(ls2g,  e0);
            ls2g8 = haddu2(ls2g8, e1);
            Pw[(wq0 + g)     * 68 + 4 * nt + t] = e0;
            Pw[(wq0 + g + 8) * 68 + 4 * nt + t] = e1;
        }
        {   // fold f16x2 partial sums to f32 (bounded magnitude per chunk)
            __half2 a = *(__half2*)&ls2g, b = *(__half2*)&ls2g8;
            lsum0 += __low2float(a) + __high2float(a);
            lsum1 += __low2float(b) + __high2float(b);
        }

        __syncwarp();

        // ---- O += P V  (7 exact k16 chunks over 112 keys) -----------------
#pragma unroll
        for (int kc = 0; kc < 7; kc++) {
            const uint32_t* pr0 = Pw + (wq0 + g)     * 68 + 8 * kc + t;
            const uint32_t* pr8 = Pw + (wq0 + g + 8) * 68 + 8 * kc + t;
            uint32_t a0 = pr0[0], a1 = pr8[0], a2 = pr0[4], a3 = pr8[4];
#pragma unroll
            for (int mt = 0; mt < 4; mt++) {
                const uint32_t* vrow = Vw + (8 * mt + g) * 68 + 8 * kc + t;
                mma_f16(Oa[mt][0], Oa[mt][1], Oa[mt][2], Oa[mt][3],
                        a0, a1, a2, a3, vrow[0], vrow[4]);
            }
        }
    }

    // ---- normalize + store -------------------------------------------------
    lsum0 += __shfl_xor_sync(0xffffffffu, lsum0, 1);
    lsum0 += __shfl_xor_sync(0xffffffffu, lsum0, 2);
    lsum1 += __shfl_xor_sync(0xffffffffu, lsum1, 1);
    lsum1 += __shfl_xor_sync(0xffffffffu, lsum1, 2);
    const float rinv0 = 1.0f / lsum0;
    const float rinv1 = 1.0f / lsum1;

    const int pA = p0 + wq0 + g;
#pragma unroll
    for (int mt = 0; mt < 4; mt++) {
        int c0 = 8 * mt + 2 * t;
        g_o[(c0       * HEADS + h) * N_POS + pA]     = Oa[mt][0] * rinv0;
        g_o[((c0 + 1) * HEADS + h) * N_POS + pA]     = Oa[mt][1] * rinv0;
        g_o[(c0       * HEADS + h) * N_POS + pA + 8] = Oa[mt][2] * rinv1;
        g_o[((c0 + 1) * HEADS + h) * N_POS + pA + 8] = Oa[mt][3] * rinv1;
    }
}

// ---------------- Kernel 4: output projection -------------------------------
__global__ __launch_bounds__(256) void out_kernel(
    const float* __restrict__ Wo, const float* __restrict__ bo,
    float* __restrict__ out)
{
    __shared__ float Xs[64 * 64];
    __shared__ float Ws[16 * 68];

    const int p0  = blockIdx.x * 64;
    const int co0 = blockIdx.y * 16;
    const int tid = threadIdx.x;
    const int tx = tid & 15, ty = tid >> 4;
    float acc[4] = {0.f, 0.f, 0.f, 0.f};

    for (int kc = 0; kc < 256; kc += 64) {
        __syncthreads();
        for (int i = tid; i < 64 * 16; i += 256) {
            int r = i >> 4, c4 = (i & 15) * 4;
            *(float4*)&Xs[r * 64 + c4] = *(const float4*)&g_o[(kc + r) * N_POS + p0 + c4];
        }
        {
            int r = tid >> 4, c4 = (tid & 15) * 4;
            *(float4*)&Ws[r * 68 + c4] = *(const float4*)&Wo[(co0 + r) * 256 + kc + c4];
        }
        __syncthreads();
#pragma unroll 8
        for (int kk = 0; kk < 64; kk++) {
            float a = Ws[ty * 68 + kk];
            float4 b = *(const float4*)&Xs[kk * 64 + tx * 4];
            acc[0] += a * b.x; acc[1] += a * b.y; acc[2] += a * b.z; acc[3] += a * b.w;
        }
    }
    float bv_ = bo[co0 + ty];
#pragma unroll
    for (int j = 0; j < 4; j++)
        out[(co0 + ty) * N_POS + p0 + tx * 4 + j] = acc[j] + bv_;
}

// ---------------- launch -----------------------------------------------------
extern "C" void kernel_launch(void* const* d_in, const int* in_sizes, int n_in,
                              void* d_out, int out_size)
{
    const float* x    = (const float*)d_in[0];
    const float* Wq   = (const float*)d_in[1];
    const float* bq   = (const float*)d_in[2];
    const float* Wk   = (const float*)d_in[3];
    const float* bk   = (const float*)d_in[4];
    const float* Wv   = (const float*)d_in[5];
    const float* bv   = (const float*)d_in[6];
    const float* Wo   = (const float*)d_in[7];
    const float* bo   = (const float*)d_in[8];
    const float* rowT = (const float*)d_in[9];
    const float* colT = (const float*)d_in[10];

    cudaFuncSetAttribute(attn_kernel,
                         cudaFuncAttributeMaxDynamicSharedMemorySize, SMEMB);

    qkv_kernel<<<dim3(49, 12), 256>>>(x, Wq, bq, Wk, bk, Wv, bv);
    bias_kernel<<<10976, 256>>>(rowT, colT);
    attn_kernel<<<392, 128, SMEMB>>>();
    out_kernel<<<dim3(49, 4), 256>>>(Wo, bo, (float*)d_out);
}

// round 12
// speedup vs baseline: 1.5166x; 1.0021x over previous
#include <cuda_runtime.h>
#include <cuda_fp16.h>
#include <math_constants.h>
#include <cstdint>

#define N_POS 3136
#define HW    56
#define MIDC  32
#define HEADS 8
#define INV   0.125f   // 1/sqrt(64)
#define LOG2E 1.4426950408889634f

// ---------------- scratch (global, no allocation in kernel_launch) ----------
__device__ float  g_q [HEADS * N_POS * MIDC];   // [h][p][m] fp32
__device__ __half g_k [HEADS * N_POS * MIDC];   // [h][p][m] fp16
__device__ __half g_vT[HEADS * MIDC * N_POS];   // [h][m][p] fp16 (transposed V)
__device__ __half g_rowb[HEADS * N_POS * HW];   // log2e*inv-scaled row bias (f16)
__device__ __half g_colb[HEADS * N_POS * HW];   // log2e*inv-scaled col bias (f16)
__device__ float g_o0[MIDC * HEADS * N_POS];    // key-half 0 partial O (unnormalized)
__device__ float g_o1[MIDC * HEADS * N_POS];    // key-half 1 partial O
__device__ float g_ls0[HEADS * N_POS];          // key-half 0 partial lsum
__device__ float g_ls1[HEADS * N_POS];          // key-half 1 partial lsum

// ---------------- helpers ----------------------------------------------------
__device__ __forceinline__ uint32_t pkh2(float lo, float hi) {
    uint32_t r;
    asm("cvt.rn.f16x2.f32 %0, %1, %2;" : "=r"(r) : "f"(hi), "f"(lo));
    return r;
}
__device__ __forceinline__ uint32_t ex2h2(uint32_t x) {
    uint32_t r; asm("ex2.approx.f16x2 %0, %1;" : "=r"(r) : "r"(x)); return r;
}
__device__ __forceinline__ uint32_t haddu2(uint32_t a, uint32_t b) {
    uint32_t r; asm("add.rn.f16x2 %0, %1, %2;" : "=r"(r) : "r"(a), "r"(b)); return r;
}
// f32-accumulator MMA (PV)
__device__ __forceinline__ void mma_f16(
    float& d0, float& d1, float& d2, float& d3,
    uint32_t a0, uint32_t a1, uint32_t a2, uint32_t a3,
    uint32_t b0, uint32_t b1)
{
    asm("mma.sync.aligned.m16n8k16.row.col.f32.f16.f16.f32 "
        "{%0,%1,%2,%3}, {%4,%5,%6,%7}, {%8,%9}, {%0,%1,%2,%3};"
        : "+f"(d0), "+f"(d1), "+f"(d2), "+f"(d3)
        : "r"(a0), "r"(a1), "r"(a2), "r"(a3), "r"(b0), "r"(b1));
}
// f16-accumulator MMA (S): D/C are 2 x f16x2
__device__ __forceinline__ void mma_f16acc(
    uint32_t& d0, uint32_t& d1,
    uint32_t a0, uint32_t a1, uint32_t a2, uint32_t a3,
    uint32_t b0, uint32_t b1)
{
    asm("mma.sync.aligned.m16n8k16.row.col.f16.f16.f16.f16 "
        "{%0,%1}, {%2,%3,%4,%5}, {%6,%7}, {%0,%1};"
        : "+r"(d0), "+r"(d1)
        : "r"(a0), "r"(a1), "r"(a2), "r"(a3), "r"(b0), "r"(b1));
}

#define CP_ASYNC16(dst_smem, src) \
    asm volatile("cp.async.cg.shared.global [%0], [%1], 16;" \
                 :: "r"((unsigned)(dst_smem)), "l"(src))
#define CP_COMMIT()  asm volatile("cp.async.commit_group;")
#define CP_WAIT0()   asm volatile("cp.async.wait_group 0;" ::: "memory")

// ---------------- Kernel 1: fused QKV projection ----------------------------
__global__ __launch_bounds__(256) void qkv_kernel(
    const float* __restrict__ x,
    const float* __restrict__ Wq, const float* __restrict__ bq,
    const float* __restrict__ Wk, const float* __restrict__ bk,
    const float* __restrict__ Wv, const float* __restrict__ bv)
{
    __shared__ float Xs[64 * 64];
    __shared__ float Ws[64 * 68];

    const int p0  = blockIdx.x * 64;
    const int by  = blockIdx.y;
    const int mat = by >> 2;
    const int dl0 = (by & 3) * 64;
    const float* W    = (mat == 0) ? Wq : (mat == 1) ? Wk : Wv;
    const float* bias = (mat == 0) ? bq : (mat == 1) ? bk : bv;

    const int tid = threadIdx.x;
    for (int i = tid; i < 64 * 16; i += 256) {
        int r = i >> 4, c4 = (i & 15) * 4;
        *(float4*)&Xs[r * 64 + c4] = *(const float4*)&x[r * N_POS + p0 + c4];
        *(float4*)&Ws[r * 68 + c4] = *(const float4*)&W[(dl0 + r) * 64 + c4];
    }
    __syncthreads();

    const int tx = tid & 15, ty = tid >> 4;
    float acc[4][4];
#pragma unroll
    for (int i = 0; i < 4; i++)
#pragma unroll
        for (int j = 0; j < 4; j++) acc[i][j] = 0.f;

#pragma unroll 8
    for (int kk = 0; kk < 64; kk++) {
        float a[4];
#pragma unroll
        for (int i = 0; i < 4; i++) a[i] = Ws[(ty * 4 + i) * 68 + kk];
        float4 b = *(const float4*)&Xs[kk * 64 + tx * 4];
#pragma unroll
        for (int i = 0; i < 4; i++) {
            acc[i][0] += a[i] * b.x; acc[i][1] += a[i] * b.y;
            acc[i][2] += a[i] * b.z; acc[i][3] += a[i] * b.w;
        }
    }

#pragma unroll
    for (int i = 0; i < 4; i++) {
        int d = dl0 + ty * 4 + i;
        float bv_ = bias[d];
        int h = d & 7, m = d >> 3;
#pragma unroll
        for (int j = 0; j < 4; j++) {
            int p = p0 + tx * 4 + j;
            float val = acc[i][j] + bv_;
            if (mat == 0)      g_q [(h * N_POS + p) * MIDC + m] = val;
            else if (mat == 1) g_k [(h * N_POS + p) * MIDC + m] = __float2half(val);
            else               g_vT[(h * MIDC + m) * N_POS + p] = __float2half(val);
        }
    }
}

// ---------------- Kernel 2: bias precompute (x INV*LOG2E, f16 out) ----------
__global__ __launch_bounds__(256) void bias_kernel(
    const float* __restrict__ rowT, const float* __restrict__ colT)
{
    int idx = blockIdx.x * 256 + threadIdx.x;
    int h   = idx / (N_POS * 112);
    int rem = idx - h * (N_POS * 112);
    int p   = rem / 112;
    int t   = rem - p * 112;
    const float* Qp = &g_q[(h * N_POS + p) * MIDC];
    const float sc = INV * LOG2E;

    if (t < HW) {
        int i = p / HW;
        const float* tr = &rowT[(t - i + 55) * 16];
        float acc = 0.f;
#pragma unroll
        for (int m = 0; m < 16; m++) acc += Qp[m] * tr[m];
        g_rowb[(h * N_POS + p) * HW + t] = __float2half(acc * sc);
    } else {
        int l = t - HW, j = p % HW;
        const float* tc = &colT[(l - j + 55) * 16];
        float acc = 0.f;
#pragma unroll
        for (int m = 0; m < 16; m++) acc += Qp[16 + m] * tc[m];
        g_colb[(h * N_POS + p) * HW + l] = __float2half(acc * sc);
    }
}

// ---------------- Kernel 3: fp16 flash attention, key-split x2 --------------
// 784 blocks = 8 heads x 49 q-tiles x 2 key-halves; 128 threads = 4 warps.
// Each block: 14 chunks of 112 keys; writes unnormalized O partial + lsum.
// smem (bytes):
//   K0 @0      : [112 keys][40 halves] (80B rows, 20-word stride)
//   K1 @8960
//   V0 @17920  : [32 ch][136 halves]   (272B rows, 68-word stride)
//   V1 @26624
//   Pm @35328  : [64 q][136 halves]    (68-word stride)
#define KOFF0 0
#define KOFF1 8960
#define VOFF0 17920
#define VOFF1 26624
#define PMOFF 35328
#define SMEMB 52736          // 4 blocks/SM

__global__ __launch_bounds__(128, 4) void attn_kernel()
{
    extern __shared__ char smc[];

    const int bx  = blockIdx.x;
    const int h   = bx / 98;
    const int rem = bx - h * 98;
    const int qt  = rem >> 1;
    const int s   = rem & 1;
    const int p0  = qt * 64;
    const int cbeg = s * 14, cend = cbeg + 14;

    const int tid = threadIdx.x;
    const int w   = tid >> 5;
    const int ln  = tid & 31;
    const int g   = ln >> 2;          // 0..7
    const int t   = ln & 3;           // 0..3
    const int wq0 = w * 16;
    const int hbase = h * N_POS;

    const unsigned sm_u32 = (unsigned)__cvta_generic_to_shared(smc);

    // ---- Q fragments (x INV*LOG2E) as packed fp16 -------------------------
    uint32_t qa[2][4];
    {
        const float sc = INV * LOG2E;
        const float* Q0 = &g_q[(hbase + p0 + wq0 + g) * MIDC];
        const float* Q8 = Q0 + 8 * MIDC;
#pragma unroll
        for (int kc = 0; kc < 2; kc++) {
            int c0 = 16 * kc + 2 * t;
            qa[kc][0] = pkh2(Q0[c0]     * sc, Q0[c0 + 1] * sc);
            qa[kc][1] = pkh2(Q8[c0]     * sc, Q8[c0 + 1] * sc);
            qa[kc][2] = pkh2(Q0[c0 + 8] * sc, Q0[c0 + 9] * sc);
            qa[kc][3] = pkh2(Q8[c0 + 8] * sc, Q8[c0 + 9] * sc);
        }
    }

    // ---- column-bias as packed f16x2 pairs (rows g and g+8) ---------------
    uint32_t cb2g[7], cb2g8[7];
    {
        const __half* C0 = &g_colb[(hbase + p0 + wq0 + g) * HW];
        const __half* C8 = C0 + 8 * HW;
#pragma unroll
        for (int nt = 0; nt < 7; nt++) {
            int c0 = 8 * nt + 2 * t;
            cb2g[nt]  = *(const uint32_t*)(C0 + c0);
            cb2g8[nt] = *(const uint32_t*)(C8 + c0);
        }
    }

    // ---- rb via gmem, prefetched one iteration ahead ----------------------
    const __half* rbg  = g_rowb + (hbase + p0 + wq0 + g) * HW;
    const __half* rbg8 = rbg + 8 * HW;
    uint32_t rbnx0 = *(const uint32_t*)(rbg  + 2 * cbeg);   // kr pair (2c, 2c+1)
    uint32_t rbnx8 = *(const uint32_t*)(rbg8 + 2 * cbeg);

    float Oa[4][4];
#pragma unroll
    for (int mt = 0; mt < 4; mt++)
#pragma unroll
        for (int j = 0; j < 4; j++) Oa[mt][j] = 0.f;
    float lsum0 = 0.f, lsum1 = 0.f;

    // ---- async tile loader: K 448x16B + V^T 448x16B -----------------------
    auto load_tile = [&](int c, int buf) {
        const uint32_t kof = sm_u32 + (buf ? KOFF1 : KOFF0);
        const uint32_t vof = sm_u32 + (buf ? VOFF1 : VOFF0);
        const __half* Kg = g_k  + (hbase + c * 112) * MIDC;
        const __half* Vg = g_vT + h * MIDC * N_POS + c * 112;
#pragma unroll 7
        for (int i = tid; i < 896; i += 128) {
            if (i < 448) {
                int r = i >> 2, cc = i & 3;
                CP_ASYNC16(kof + r * 80 + cc * 16, Kg + r * 32 + cc * 8);
            } else {
                int j = i - 448;
                int m = j / 14, t14 = j - m * 14;
                CP_ASYNC16(vof + m * 272 + t14 * 16, Vg + m * N_POS + t14 * 8);
            }
        }
        CP_COMMIT();
    };

    load_tile(cbeg, cbeg & 1);

    for (int c = cbeg; c < cend; c++) {
        const int buf = c & 1;
        CP_WAIT0();
        __syncthreads();
        if (c + 1 < cend) load_tile(c + 1, (c + 1) & 1);

        const uint32_t* Ku = (const uint32_t*)(smc + (buf ? KOFF1 : KOFF0));
        const uint32_t* Vw = (const uint32_t*)(smc + (buf ? VOFF1 : VOFF0));
        uint32_t* Pw = (uint32_t*)(smc + PMOFF);

        // current rb pair; prefetch next
        uint32_t rbc0 = rbnx0, rbc8 = rbnx8;
        if (c + 1 < cend) {
            rbnx0 = *(const uint32_t*)(rbg  + 2 * (c + 1));
            rbnx8 = *(const uint32_t*)(rbg8 + 2 * (c + 1));
        }
        uint32_t r2[2][2];
        {
            __half2 a = *(__half2*)&rbc0, b = *(__half2*)&rbc8;
            __half2 t00 = __half2half2(__low2half(a)),  t10 = __half2half2(__high2half(a));
            __half2 t01 = __half2half2(__low2half(b)),  t11 = __half2half2(__high2half(b));
            r2[0][0] = *(uint32_t*)&t00; r2[1][0] = *(uint32_t*)&t10;
            r2[0][1] = *(uint32_t*)&t01; r2[1][1] = *(uint32_t*)&t11;
        }

        uint32_t ls2g = 0u, ls2g8 = 0u;   // f16x2 zero

        // ---- S = Q K^T (f16 acc, bias as C); P = ex2.f16x2 ---------------
#pragma unroll
        for (int nt = 0; nt < 14; nt++) {
            const int sel = (nt < 7) ? 0 : 1;
            const int ci  = (nt < 7) ? nt : nt - 7;
            const uint32_t* krow = Ku + (8 * nt + g) * 20 + t;
            uint32_t b00 = krow[0], b01 = krow[4], b10 = krow[8], b11 = krow[12];
            uint32_t d0 = haddu2(r2[sel][0], cb2g[ci]);
            uint32_t d1 = haddu2(r2[sel][1], cb2g8[ci]);
            mma_f16acc(d0, d1, qa[0][0], qa[0][1], qa[0][2], qa[0][3], b00, b01);
            mma_f16acc(d0, d1, qa[1][0], qa[1][1], qa[1][2], qa[1][3], b10, b11);
            uint32_t e0 = ex2h2(d0);
            uint32_t e1 = ex2h2(d1);
            ls2g  = haddu2(ls2g,  e0);
            ls2g8 = haddu2(ls2g8, e1);
            Pw[(wq0 + g)     * 68 + 4 * nt + t] = e0;
            Pw[(wq0 + g + 8) * 68 + 4 * nt + t] = e1;
        }
        {
            __half2 a = *(__half2*)&ls2g, b = *(__half2*)&ls2g8;
            lsum0 += __low2float(a) + __high2float(a);
            lsum1 += __low2float(b) + __high2float(b);
        }

        __syncwarp();

        // ---- O += P V  (7 exact k16 chunks over 112 keys) -----------------
#pragma unroll
        for (int kc = 0; kc < 7; kc++) {
            const uint32_t* pr0 = Pw + (wq0 + g)     * 68 + 8 * kc + t;
            const uint32_t* pr8 = Pw + (wq0 + g + 8) * 68 + 8 * kc + t;
            uint32_t a0 = pr0[0], a1 = pr8[0], a2 = pr0[4], a3 = pr8[4];
#pragma unroll
            for (int mt = 0; mt < 4; mt++) {
                const uint32_t* vrow = Vw + (8 * mt + g) * 68 + 8 * kc + t;
                mma_f16(Oa[mt][0], Oa[mt][1], Oa[mt][2], Oa[mt][3],
                        a0, a1, a2, a3, vrow[0], vrow[4]);
            }
        }
    }

    // ---- reduce lsum over group, store partials ---------------------------
    lsum0 += __shfl_xor_sync(0xffffffffu, lsum0, 1);
    lsum0 += __shfl_xor_sync(0xffffffffu, lsum0, 2);
    lsum1 += __shfl_xor_sync(0xffffffffu, lsum1, 1);
    lsum1 += __shfl_xor_sync(0xffffffffu, lsum1, 2);

    float* Op = s ? g_o1 : g_o0;
    float* Lp = s ? g_ls1 : g_ls0;
    const int pA = p0 + wq0 + g;
    if (t == 0) {
        Lp[h * N_POS + pA]     = lsum0;
        Lp[h * N_POS + pA + 8] = lsum1;
    }
#pragma unroll
    for (int mt = 0; mt < 4; mt++) {
        int c0 = 8 * mt + 2 * t;
        Op[(c0       * HEADS + h) * N_POS + pA]     = Oa[mt][0];
        Op[((c0 + 1) * HEADS + h) * N_POS + pA]     = Oa[mt][1];
        Op[(c0       * HEADS + h) * N_POS + pA + 8] = Oa[mt][2];
        Op[((c0 + 1) * HEADS + h) * N_POS + pA + 8] = Oa[mt][3];
    }
}

// ---------------- Kernel 4: output projection + key-half combine ------------
__global__ __launch_bounds__(256) void out_kernel(
    const float* __restrict__ Wo, const float* __restrict__ bo,
    float* __restrict__ out)
{
    __shared__ float Xs[64 * 64];
    __shared__ float Ws[16 * 68];
    __shared__ float rinvs[8 * 64];

    const int p0  = blockIdx.x * 64;
    const int co0 = blockIdx.y * 16;
    const int tid = threadIdx.x;
    const int tx = tid & 15, ty = tid >> 4;

    // rinv[h][j] = 1 / (ls0 + ls1)
    for (int i = tid; i < 512; i += 256) {
        int hh = i >> 6, j = i & 63;
        rinvs[i] = 1.0f / (g_ls0[hh * N_POS + p0 + j] + g_ls1[hh * N_POS + p0 + j]);
    }

    float acc[4] = {0.f, 0.f, 0.f, 0.f};

    for (int kc = 0; kc < 256; kc += 64) {
        __syncthreads();
        for (int i = tid; i < 64 * 16; i += 256) {
            int r = i >> 4, c4 = (i & 15) * 4;
            float4 a = *(const float4*)&g_o0[(kc + r) * N_POS + p0 + c4];
            float4 b = *(const float4*)&g_o1[(kc + r) * N_POS + p0 + c4];
            const float* rv = &rinvs[(r & 7) * 64 + c4];
            float4 v;
            v.x = (a.x + b.x) * rv[0];
            v.y = (a.y + b.y) * rv[1];
            v.z = (a.z + b.z) * rv[2];
            v.w = (a.w + b.w) * rv[3];
            *(float4*)&Xs[r * 64 + c4] = v;
        }
        {
            int r = tid >> 4, c4 = (tid & 15) * 4;
            *(float4*)&Ws[r * 68 + c4] = *(const float4*)&Wo[(co0 + r) * 256 + kc + c4];
        }
        __syncthreads();
#pragma unroll 8
        for (int kk = 0; kk < 64; kk++) {
            float a = Ws[ty * 68 + kk];
            float4 b = *(const float4*)&Xs[kk * 64 + tx * 4];
            acc[0] += a * b.x; acc[1] += a * b.y; acc[2] += a * b.z; acc[3] += a * b.w;
        }
    }
    float bv_ = bo[co0 + ty];
#pragma unroll
    for (int j = 0; j < 4; j++)
        out[(co0 + ty) * N_POS + p0 + tx * 4 + j] = acc[j] + bv_;
}

// ---------------- launch -----------------------------------------------------
extern "C" void kernel_launch(void* const* d_in, const int* in_sizes, int n_in,
                              void* d_out, int out_size)
{
    const float* x    = (const float*)d_in[0];
    const float* Wq   = (const float*)d_in[1];
    const float* bq   = (const float*)d_in[2];
    const float* Wk   = (const float*)d_in[3];
    const float* bk   = (const float*)d_in[4];
    const float* Wv   = (const float*)d_in[5];
    const float* bv   = (const float*)d_in[6];
    const float* Wo   = (const float*)d_in[7];
    const float* bo   = (const float*)d_in[8];
    const float* rowT = (const float*)d_in[9];
    const float* colT = (const float*)d_in[10];

    cudaFuncSetAttribute(attn_kernel,
                         cudaFuncAttributeMaxDynamicSharedMemorySize, SMEMB);

    qkv_kernel<<<dim3(49, 12), 256>>>(x, Wq, bq, Wk, bk, Wv, bv);
    bias_kernel<<<10976, 256>>>(rowT, colT);
    attn_kernel<<<784, 128, SMEMB>>>();
    out_kernel<<<dim3(49, 4), 256>>>(Wo, bo, (float*)d_out);
}